// round 11
// baseline (speedup 1.0000x reference)
#include <cuda_runtime.h>
#include <math.h>

#define NN 50000
#define FF 128

// ---------------- scratch (device globals; no allocation) ----------------
__device__ __align__(16) float d_xt1[NN * 64];   // [N][4][16], slot15 = ak1
__device__ float d_aq1[NN * 4];
__device__ __align__(16) float d_agg1[NN * 16];  // slot15 = denom
__device__ float d_h1[NN * 16];
__device__ __align__(16) float d_xt2[NN * 64];   // [N][4][16], slot10 = ak2
__device__ float d_aq2[NN * 4];
__device__ __align__(16) float d_agg2[NN * 12];  // slot10 = denom
__device__ float d_h2[NN * 10];
// padded weight layout: [ft][f][cg(8)][12], col = cg*9 + c (c<9), zero pad
__device__ __align__(16) float d_CW1p[4 * 32 * 96];
__device__ float d_CW2[15 * 48];    // cols 0..39 = W2, 40..43 = W2@q2, 44..47 = W2@k2
__device__ float d_stats[64];
__device__ float d_bn1s[15], d_bn1b[15], d_bn2s[10], d_bn2b[10];
__device__ float d_c1, d_c2;

// ---------------- helpers ----------------
__device__ __forceinline__ void red4(float* p, float a, float b, float c, float d) {
    asm volatile("red.global.add.v4.f32 [%0], {%1,%2,%3,%4};"
                 :: "l"(p), "f"(a), "f"(b), "f"(c), "f"(d) : "memory");
}

// ---------------- init ----------------
__global__ void k_zero() {
    const int tot = NN * 16 + NN * 12 + 64;
    for (int i = blockIdx.x * blockDim.x + threadIdx.x; i < tot; i += gridDim.x * blockDim.x) {
        if (i < NN * 16)            d_agg1[i] = 0.f;
        else if (i < NN * 28)       d_agg2[i - NN * 16] = 0.f;
        else                        d_stats[i - NN * 28] = 0.f;
    }
}

// ---------------- weight prep (padded layout, cg stride 12) ----------------
__global__ void k_build1(const float* __restrict__ W1, const float* __restrict__ q1,
                         const float* __restrict__ k1) {
    int i = blockIdx.x * 256 + threadIdx.x;
    if (i >= 4 * 32 * 96) return;
    int c12 = i % 12, cg = (i / 12) & 7, f = (i / 96) & 31, ft = i / 3072;
    int fg = ft * 32 + f;
    float v = 0.f;
    int col = cg * 9 + c12;
    if (c12 < 9 && col < 68) {
        if (col < 60) {
            int r = col / 15, o = col % 15;
            v = W1[(r * 128 + fg) * 15 + o];
        } else if (col < 64) {
            int r = col - 60; float s = 0.f;
            for (int o = 0; o < 15; ++o) s += W1[(r * 128 + fg) * 15 + o] * q1[o];
            v = s;
        } else {
            int r = col - 64; float s = 0.f;
            for (int o = 0; o < 15; ++o) s += W1[(r * 128 + fg) * 15 + o] * k1[o];
            v = s;
        }
    }
    d_CW1p[i] = v;
}

__global__ void k_build2(const float* __restrict__ W2, const float* __restrict__ q2,
                         const float* __restrict__ k2,
                         const float* __restrict__ We1, const float* __restrict__ e1,
                         const float* __restrict__ We2, const float* __restrict__ e2) {
    int i = blockIdx.x * 256 + threadIdx.x;
    if (i == 0) {
        float s = 0.f;
        for (int o = 0; o < 15; ++o) s += We1[o] * e1[o];
        d_c1 = s;
        float t = 0.f;
        for (int o = 0; o < 10; ++o) t += We2[o] * e2[o];
        d_c2 = t;
    }
    if (i >= 15 * 48) return;
    int f = i / 48, c = i % 48;
    float v;
    if (c < 40) {
        int r = c / 10, o = c % 10;
        v = W2[(r * 15 + f) * 10 + o];
    } else if (c < 44) {
        int r = c - 40; float s = 0.f;
        for (int o = 0; o < 10; ++o) s += W2[(r * 15 + f) * 10 + o] * q2[o];
        v = s;
    } else {
        int r = c - 44; float s = 0.f;
        for (int o = 0; o < 10; ++o) s += W2[(r * 15 + f) * 10 + o] * k2[o];
        v = s;
    }
    d_CW2[i] = v;
}

// ---------------- layer-1 GEMM: [N,128] @ [128,68] ----------------
// 256 threads = 32 node-groups(x4 nodes) x 8 col-groups(x9 cols).
// 128 nodes/block -> grid 391 -> ~21 warps/SM; 36 FMA per 13 smem floats.
__global__ void __launch_bounds__(256) k_gemm1(const float* __restrict__ x, int n_nodes) {
    __shared__ __align__(16) float xs[128 * 36];  // 128 nodes x 32 f, stride 36
    __shared__ __align__(16) float ws[32 * 96];   // [f][cg*12 + c]
    const int tid = threadIdx.x;
    const int nbase = blockIdx.x * 128;
    const int ng = tid >> 3, cg = tid & 7;        // ng 0..31 (4 nodes), cg 0..7 (9 cols)
    const int n0 = ng * 4;

    float acc[4][9];
#pragma unroll
    for (int i = 0; i < 4; ++i)
#pragma unroll
        for (int c = 0; c < 9; ++c) acc[i][c] = 0.f;

    const bool full = (nbase + 128 <= n_nodes);

    for (int ft = 0; ft < 4; ++ft) {
        // x tile: 128 nodes x 32 f = 1024 float4; 4 per thread
#pragma unroll
        for (int k = 0; k < 4; ++k) {
            int idx = k * 256 + tid;
            int nl = idx >> 3, q = idx & 7;
            int n = nbase + nl;
            float4 v = make_float4(0.f, 0.f, 0.f, 0.f);
            if (full || n < n_nodes)
                v = *reinterpret_cast<const float4*>(x + (size_t)n * FF + ft * 32 + q * 4);
            *reinterpret_cast<float4*>(&xs[nl * 36 + q * 4]) = v;
        }
        // ws tile: 3072 floats = 768 float4; 3 per thread
        {
            const float4* src = reinterpret_cast<const float4*>(d_CW1p + ft * 3072);
            float4* dst = reinterpret_cast<float4*>(ws);
#pragma unroll
            for (int k = 0; k < 3; ++k) dst[k * 256 + tid] = src[k * 256 + tid];
        }
        __syncthreads();

#pragma unroll
        for (int f = 0; f < 32; ++f) {
            const float* wr = &ws[f * 96 + cg * 12];
            float4 wa = *reinterpret_cast<const float4*>(wr);
            float4 wb = *reinterpret_cast<const float4*>(wr + 4);
            float w8 = wr[8];
            float x0 = xs[(n0 + 0) * 36 + f];
            float x1 = xs[(n0 + 1) * 36 + f];
            float x2 = xs[(n0 + 2) * 36 + f];
            float x3 = xs[(n0 + 3) * 36 + f];
#pragma unroll
            for (int i = 0; i < 4; ++i) {
                float xi = (i == 0) ? x0 : (i == 1) ? x1 : (i == 2) ? x2 : x3;
                acc[i][0] += xi * wa.x;
                acc[i][1] += xi * wa.y;
                acc[i][2] += xi * wa.z;
                acc[i][3] += xi * wa.w;
                acc[i][4] += xi * wb.x;
                acc[i][5] += xi * wb.y;
                acc[i][6] += xi * wb.z;
                acc[i][7] += xi * wb.w;
                acc[i][8] += xi * w8;
            }
        }
        __syncthreads();
    }

#pragma unroll
    for (int i = 0; i < 4; ++i) {
        int n = nbase + n0 + i;
        if (n >= n_nodes) break;
#pragma unroll
        for (int c = 0; c < 9; ++c) {
            int col = cg * 9 + c;
            if (col >= 68) break;
            float v = acc[i][c];
            if (col < 60)      d_xt1[n * 64 + (col / 15) * 16 + (col % 15)] = v;
            else if (col < 64) d_aq1[n * 4 + col - 60] = v;
            else               d_xt1[n * 64 + (col - 64) * 16 + 15] = v;   // ak packed
        }
    }
}

// ---------------- edge pass 1 ----------------
__global__ void __launch_bounds__(256) k_edge1(const int* __restrict__ ei, const int* __restrict__ et,
                                               const float* __restrict__ ea, int ne) {
    int e = blockIdx.x * 256 + threadIdx.x;
    if (e >= ne) return;
    int s = ei[e], d = ei[ne + e];
    int r = et[e];
    const float4* xp = reinterpret_cast<const float4*>(d_xt1 + ((size_t)s * 4 + r) * 16);
    float4 v0 = xp[0], v1 = xp[1], v2 = xp[2], v3 = xp[3];   // v3.w = ak[s,r]
    float a = d_aq1[d * 4 + r] + v3.w + ea[e] * d_c1;
    a = (a > 0.f) ? a : 0.2f * a;
    float ex = __expf(a);
    float* ag = d_agg1 + (size_t)d * 16;
    red4(ag + 0,  ex * v0.x, ex * v0.y, ex * v0.z, ex * v0.w);
    red4(ag + 4,  ex * v1.x, ex * v1.y, ex * v1.z, ex * v1.w);
    red4(ag + 8,  ex * v2.x, ex * v2.y, ex * v2.z, ex * v2.w);
    red4(ag + 12, ex * v3.x, ex * v3.y, ex * v3.z, ex);      // .w accumulates denom
}

// ---------------- post layer 1 ----------------
__global__ void __launch_bounds__(256) k_post1(const float* __restrict__ b1, int n_nodes) {
    int n = blockIdx.x * 256 + threadIdx.x;
    float h[15];
#pragma unroll
    for (int o = 0; o < 15; ++o) h[o] = 0.f;
    if (n < n_nodes) {
        float inv = 1.f / (d_agg1[n * 16 + 15] + 1e-16f);
#pragma unroll
        for (int o = 0; o < 15; ++o) {
            h[o] = d_agg1[n * 16 + o] * inv + b1[o];
            d_h1[n * 16 + o] = h[o];
        }
    }
    __shared__ float ssum[15], ssq[15];
    if (threadIdx.x < 15) { ssum[threadIdx.x] = 0.f; ssq[threadIdx.x] = 0.f; }
    __syncthreads();
#pragma unroll
    for (int o = 0; o < 15; ++o) {
        float s = h[o], s2 = h[o] * h[o];
        for (int off = 16; off; off >>= 1) {
            s  += __shfl_down_sync(0xffffffffu, s, off);
            s2 += __shfl_down_sync(0xffffffffu, s2, off);
        }
        if ((threadIdx.x & 31) == 0) { atomicAdd(&ssum[o], s); atomicAdd(&ssq[o], s2); }
    }
    __syncthreads();
    if (threadIdx.x < 15)                               atomicAdd(&d_stats[threadIdx.x], ssum[threadIdx.x]);
    else if (threadIdx.x >= 16 && threadIdx.x < 31)     atomicAdd(&d_stats[threadIdx.x], ssq[threadIdx.x - 16]);
}

__global__ void k_bnfin1(const float* __restrict__ g, const float* __restrict__ beta, int n_nodes) {
    int o = threadIdx.x;
    if (o < 15) {
        float invn = 1.f / (float)n_nodes;
        float mean = d_stats[o] * invn;
        float var  = d_stats[16 + o] * invn - mean * mean;
        float sc = g[o] * rsqrtf(var + 1e-5f);
        d_bn1s[o] = sc;
        d_bn1b[o] = beta[o] - mean * sc;
    }
}

// ---------------- layer-2: BN+ELU then [N,15] @ [15,48] ----------------
__global__ void __launch_bounds__(256) k_gemm2(int n_nodes) {
    __shared__ float w2s[720];
    for (int i = threadIdx.x; i < 720; i += 256) w2s[i] = d_CW2[i];
    __syncthreads();
    int n = blockIdx.x * 256 + threadIdx.x;
    if (n >= n_nodes) return;
    float x2[15];
#pragma unroll
    for (int o = 0; o < 15; ++o) {
        float v = d_h1[n * 16 + o] * d_bn1s[o] + d_bn1b[o];
        x2[o] = (v > 0.f) ? v : expm1f(v);
    }
    float outv[48];
#pragma unroll
    for (int c = 0; c < 48; ++c) {
        float s = 0.f;
#pragma unroll
        for (int i = 0; i < 15; ++i) s += x2[i] * w2s[i * 48 + c];
        outv[c] = s;
    }
#pragma unroll
    for (int c = 0; c < 40; ++c) d_xt2[n * 64 + (c / 10) * 16 + (c % 10)] = outv[c];
#pragma unroll
    for (int r = 0; r < 4; ++r) {
        d_aq2[n * 4 + r] = outv[40 + r];
        d_xt2[n * 64 + r * 16 + 10] = outv[44 + r];   // ak2 packed
        d_xt2[n * 64 + r * 16 + 11] = 0.f;
    }
}

// ---------------- edge pass 2 ----------------
__global__ void __launch_bounds__(256) k_edge2(const int* __restrict__ ei, const int* __restrict__ et,
                                               const float* __restrict__ ea, int ne) {
    int e = blockIdx.x * 256 + threadIdx.x;
    if (e >= ne) return;
    int s = ei[e], d = ei[ne + e];
    int r = et[e];
    const float4* xp = reinterpret_cast<const float4*>(d_xt2 + ((size_t)s * 4 + r) * 16);
    float4 v0 = xp[0], v1 = xp[1], v2 = xp[2];   // v2.z = ak2[s,r]
    float a = d_aq2[d * 4 + r] + v2.z + ea[e] * d_c2;
    a = (a > 0.f) ? a : 0.2f * a;
    float ex = __expf(a);
    float* ag = d_agg2 + (size_t)d * 12;
    red4(ag + 0, ex * v0.x, ex * v0.y, ex * v0.z, ex * v0.w);
    red4(ag + 4, ex * v1.x, ex * v1.y, ex * v1.z, ex * v1.w);
    red4(ag + 8, ex * v2.x, ex * v2.y, ex, 0.f);             // slot10 = denom
}

// ---------------- post layer 2 ----------------
__global__ void __launch_bounds__(256) k_post2(const float* __restrict__ b2, int n_nodes) {
    int n = blockIdx.x * 256 + threadIdx.x;
    float h[10];
#pragma unroll
    for (int o = 0; o < 10; ++o) h[o] = 0.f;
    if (n < n_nodes) {
        float inv = 1.f / (d_agg2[n * 12 + 10] + 1e-16f);
#pragma unroll
        for (int o = 0; o < 10; ++o) {
            h[o] = d_agg2[n * 12 + o] * inv + b2[o];
            d_h2[n * 10 + o] = h[o];
        }
    }
    __shared__ float ssum[10], ssq[10];
    if (threadIdx.x < 10) { ssum[threadIdx.x] = 0.f; ssq[threadIdx.x] = 0.f; }
    __syncthreads();
#pragma unroll
    for (int o = 0; o < 10; ++o) {
        float s = h[o], s2 = h[o] * h[o];
        for (int off = 16; off; off >>= 1) {
            s  += __shfl_down_sync(0xffffffffu, s, off);
            s2 += __shfl_down_sync(0xffffffffu, s2, off);
        }
        if ((threadIdx.x & 31) == 0) { atomicAdd(&ssum[o], s); atomicAdd(&ssq[o], s2); }
    }
    __syncthreads();
    if (threadIdx.x < 10)                               atomicAdd(&d_stats[32 + threadIdx.x], ssum[threadIdx.x]);
    else if (threadIdx.x >= 16 && threadIdx.x < 26)     atomicAdd(&d_stats[48 + threadIdx.x - 16], ssq[threadIdx.x - 16]);
}

__global__ void k_bnfin2(const float* __restrict__ g, const float* __restrict__ beta, int n_nodes) {
    int o = threadIdx.x;
    if (o < 10) {
        float invn = 1.f / (float)n_nodes;
        float mean = d_stats[32 + o] * invn;
        float var  = d_stats[48 + o] * invn - mean * mean;
        float sc = g[o] * rsqrtf(var + 1e-5f);
        d_bn2s[o] = sc;
        d_bn2b[o] = beta[o] - mean * sc;
    }
}

// ---------------- head ----------------
__global__ void __launch_bounds__(256) k_head(const float* __restrict__ wh, const float* __restrict__ bh,
                                              float* __restrict__ out, int n_nodes) {
    int n = blockIdx.x * 256 + threadIdx.x;
    if (n >= n_nodes) return;
    float s = bh[0];
#pragma unroll
    for (int o = 0; o < 10; ++o) {
        float v = d_h2[n * 10 + o] * d_bn2s[o] + d_bn2b[o];
        v = (v > 0.f) ? v : expm1f(v);
        s += v * wh[o];
    }
    out[n] = s;
}

// ---------------- launch ----------------
extern "C" void kernel_launch(void* const* d_in, const int* in_sizes, int n_in,
                              void* d_out, int out_size) {
    const float* x   = (const float*)d_in[0];
    const int*   ei  = (const int*)  d_in[1];
    const int*   et  = (const int*)  d_in[2];
    const float* ea  = (const float*)d_in[3];
    const float* W1  = (const float*)d_in[4];
    const float* q1  = (const float*)d_in[5];
    const float* k1  = (const float*)d_in[6];
    const float* e1  = (const float*)d_in[7];
    const float* We1 = (const float*)d_in[8];
    const float* b1  = (const float*)d_in[9];
    const float* W2  = (const float*)d_in[10];
    const float* q2  = (const float*)d_in[11];
    const float* k2  = (const float*)d_in[12];
    const float* e2  = (const float*)d_in[13];
    const float* We2 = (const float*)d_in[14];
    const float* b2  = (const float*)d_in[15];
    const float* g1  = (const float*)d_in[16];
    const float* bt1 = (const float*)d_in[17];
    const float* g2  = (const float*)d_in[18];
    const float* bt2 = (const float*)d_in[19];
    const float* wh  = (const float*)d_in[20];
    const float* bh  = (const float*)d_in[21];
    float* out = (float*)d_out;

    int n  = in_sizes[0] / FF;
    int ne = in_sizes[1] / 2;

    k_zero<<<2048, 256>>>();
    k_build1<<<(4 * 32 * 96 + 255) / 256, 256>>>(W1, q1, k1);
    k_build2<<<3, 256>>>(W2, q2, k2, We1, e1, We2, e2);
    k_gemm1<<<(n + 127) / 128, 256>>>(x, n);
    k_edge1<<<(ne + 255) / 256, 256>>>(ei, et, ea, ne);
    k_post1<<<(n + 255) / 256, 256>>>(b1, n);
    k_bnfin1<<<1, 32>>>(g1, bt1, n);
    k_gemm2<<<(n + 255) / 256, 256>>>(n);
    k_edge2<<<(ne + 255) / 256, 256>>>(ei, et, ea, ne);
    k_post2<<<(n + 255) / 256, 256>>>(b2, n);
    k_bnfin2<<<1, 32>>>(g2, bt2, n);
    k_head<<<(n + 255) / 256, 256>>>(wh, bh, out, n);
}

// round 14
// speedup vs baseline: 1.5938x; 1.5938x over previous
#include <cuda_runtime.h>
#include <math.h>

#define NN 50000
#define FF 128

// ---------------- scratch (device globals; no allocation) ----------------
__device__ __align__(16) float d_xt1[NN * 64];   // [N][4][16], slot15 = ak1
__device__ float d_aq1[NN * 4];
__device__ __align__(16) float d_agg1[NN * 16];  // slot15 = denom
__device__ float d_h1[NN * 16];
__device__ __align__(16) float d_xt2[NN * 64];   // [N][4][16], slot10 = ak2
__device__ float d_aq2[NN * 4];
__device__ __align__(16) float d_agg2[NN * 12];  // slot10 = denom
__device__ float d_h2[NN * 10];
// padded weight layout: [ft][f][cg(16)][8], col = cg*5 + c (c<5), zero pad
__device__ __align__(16) float d_CW1p[4 * 32 * 128];
__device__ float d_CW2[15 * 48];    // cols 0..39 = W2, 40..43 = W2@q2, 44..47 = W2@k2
__device__ float d_stats[64];
__device__ float d_c1, d_c2;

// ---------------- helpers ----------------
__device__ __forceinline__ void red4(float* p, float a, float b, float c, float d) {
    asm volatile("red.global.add.v4.f32 [%0], {%1,%2,%3,%4};"
                 :: "l"(p), "f"(a), "f"(b), "f"(c), "f"(d) : "memory");
}

// ---------------- fused init: zero + build1 + build2 ----------------
#define ZT (NN * 4 + NN * 3 + 16)          // float4 count to zero
#define B1N (4 * 32 * 128)
#define B2N (15 * 48)

__global__ void __launch_bounds__(256) k_init(
        const float* __restrict__ W1, const float* __restrict__ q1, const float* __restrict__ k1,
        const float* __restrict__ W2, const float* __restrict__ q2, const float* __restrict__ k2,
        const float* __restrict__ We1, const float* __restrict__ e1,
        const float* __restrict__ We2, const float* __restrict__ e2) {
    int i = blockIdx.x * 256 + threadIdx.x;
    if (i < ZT) {
        float4 z = make_float4(0.f, 0.f, 0.f, 0.f);
        if (i < NN * 4)                 reinterpret_cast<float4*>(d_agg1)[i] = z;
        else if (i < NN * 7)            reinterpret_cast<float4*>(d_agg2)[i - NN * 4] = z;
        else                            reinterpret_cast<float4*>(d_stats)[i - NN * 7] = z;
        return;
    }
    i -= ZT;
    if (i < B1N) {
        int c8 = i & 7, cg = (i >> 3) & 15, f = (i >> 7) & 31, ft = i >> 12;
        int fg = ft * 32 + f;
        float v = 0.f;
        int col = cg * 5 + c8;
        if (c8 < 5 && col < 68) {
            if (col < 60) {
                int r = col / 15, o = col % 15;
                v = W1[(r * 128 + fg) * 15 + o];
            } else if (col < 64) {
                int r = col - 60; float s = 0.f;
                for (int o = 0; o < 15; ++o) s += W1[(r * 128 + fg) * 15 + o] * q1[o];
                v = s;
            } else {
                int r = col - 64; float s = 0.f;
                for (int o = 0; o < 15; ++o) s += W1[(r * 128 + fg) * 15 + o] * k1[o];
                v = s;
            }
        }
        d_CW1p[i] = v;
        return;
    }
    i -= B1N;
    if (i == 0) {
        float s = 0.f;
        for (int o = 0; o < 15; ++o) s += We1[o] * e1[o];
        d_c1 = s;
        float t = 0.f;
        for (int o = 0; o < 10; ++o) t += We2[o] * e2[o];
        d_c2 = t;
    }
    if (i < B2N) {
        int f = i / 48, c = i % 48;
        float v;
        if (c < 40) {
            int r = c / 10, o = c % 10;
            v = W2[(r * 15 + f) * 10 + o];
        } else if (c < 44) {
            int r = c - 40; float s = 0.f;
            for (int o = 0; o < 10; ++o) s += W2[(r * 15 + f) * 10 + o] * q2[o];
            v = s;
        } else {
            int r = c - 44; float s = 0.f;
            for (int o = 0; o < 10; ++o) s += W2[(r * 15 + f) * 10 + o] * k2[o];
            v = s;
        }
        d_CW2[i] = v;
    }
}

// ---------------- layer-1 GEMM: [N,128] @ [128,68] ----------------
// 256 threads = 16 node-groups(x4 nodes) x 16 col-groups(x5 cols).
// 64 nodes/block -> grid 782; 20 FMA per 6 LDS; ~55 regs -> 4 blocks/SM.
__global__ void __launch_bounds__(256) k_gemm1(const float* __restrict__ x, int n_nodes) {
    __shared__ __align__(16) float xs[64 * 36];    // 64 nodes x 32 f, stride 36
    __shared__ __align__(16) float ws[32 * 128];   // [f][cg*8 + c]
    const int tid = threadIdx.x;
    const int nbase = blockIdx.x * 64;
    const int ng = tid >> 4, cg = tid & 15;        // ng 0..15 (4 nodes), cg 0..15 (5 cols)
    const int n0 = ng * 4;

    float acc[4][5];
#pragma unroll
    for (int i = 0; i < 4; ++i)
#pragma unroll
        for (int c = 0; c < 5; ++c) acc[i][c] = 0.f;

    const bool full = (nbase + 64 <= n_nodes);

    for (int ft = 0; ft < 4; ++ft) {
        // x tile: 64 nodes x 32 f = 512 float4; 2 per thread
#pragma unroll
        for (int k = 0; k < 2; ++k) {
            int idx = k * 256 + tid;
            int nl = idx >> 3, q = idx & 7;
            int n = nbase + nl;
            float4 v = make_float4(0.f, 0.f, 0.f, 0.f);
            if (full || n < n_nodes)
                v = *reinterpret_cast<const float4*>(x + (size_t)n * FF + ft * 32 + q * 4);
            *reinterpret_cast<float4*>(&xs[nl * 36 + q * 4]) = v;
        }
        // ws tile: 4096 floats = 1024 float4; 4 per thread
        {
            const float4* src = reinterpret_cast<const float4*>(d_CW1p + ft * 4096);
            float4* dst = reinterpret_cast<float4*>(ws);
#pragma unroll
            for (int k = 0; k < 4; ++k) dst[k * 256 + tid] = src[k * 256 + tid];
        }
        __syncthreads();

#pragma unroll
        for (int f = 0; f < 32; ++f) {
            const float* wr = &ws[f * 128 + cg * 8];
            float4 wa = *reinterpret_cast<const float4*>(wr);
            float w4 = wr[4];
            float x0 = xs[(n0 + 0) * 36 + f];
            float x1 = xs[(n0 + 1) * 36 + f];
            float x2 = xs[(n0 + 2) * 36 + f];
            float x3 = xs[(n0 + 3) * 36 + f];
#pragma unroll
            for (int i = 0; i < 4; ++i) {
                float xi = (i == 0) ? x0 : (i == 1) ? x1 : (i == 2) ? x2 : x3;
                acc[i][0] += xi * wa.x;
                acc[i][1] += xi * wa.y;
                acc[i][2] += xi * wa.z;
                acc[i][3] += xi * wa.w;
                acc[i][4] += xi * w4;
            }
        }
        __syncthreads();
    }

#pragma unroll
    for (int i = 0; i < 4; ++i) {
        int n = nbase + n0 + i;
        if (n >= n_nodes) break;
#pragma unroll
        for (int c = 0; c < 5; ++c) {
            int col = cg * 5 + c;
            if (col >= 68) break;
            float v = acc[i][c];
            if (col < 60)      d_xt1[n * 64 + (col / 15) * 16 + (col % 15)] = v;
            else if (col < 64) d_aq1[n * 4 + col - 60] = v;
            else               d_xt1[n * 64 + (col - 64) * 16 + 15] = v;   // ak packed
        }
    }
}

// ---------------- edge pass 1 ----------------
__global__ void __launch_bounds__(256) k_edge1(const int* __restrict__ ei, const int* __restrict__ et,
                                               const float* __restrict__ ea, int ne) {
    int e = blockIdx.x * 256 + threadIdx.x;
    if (e >= ne) return;
    int s = ei[e], d = ei[ne + e];
    int r = et[e];
    const float4* xp = reinterpret_cast<const float4*>(d_xt1 + ((size_t)s * 4 + r) * 16);
    float4 v0 = xp[0], v1 = xp[1], v2 = xp[2], v3 = xp[3];   // v3.w = ak[s,r]
    float a = d_aq1[d * 4 + r] + v3.w + ea[e] * d_c1;
    a = (a > 0.f) ? a : 0.2f * a;
    float ex = __expf(a);
    float* ag = d_agg1 + (size_t)d * 16;
    red4(ag + 0,  ex * v0.x, ex * v0.y, ex * v0.z, ex * v0.w);
    red4(ag + 4,  ex * v1.x, ex * v1.y, ex * v1.z, ex * v1.w);
    red4(ag + 8,  ex * v2.x, ex * v2.y, ex * v2.z, ex * v2.w);
    red4(ag + 12, ex * v3.x, ex * v3.y, ex * v3.z, ex);      // .w accumulates denom
}

// ---------------- post layer 1: normalize + bias, BN stats ----------------
__global__ void __launch_bounds__(256) k_post1(const float* __restrict__ b1, int n_nodes) {
    int n = blockIdx.x * 256 + threadIdx.x;
    float h[15];
#pragma unroll
    for (int o = 0; o < 15; ++o) h[o] = 0.f;
    if (n < n_nodes) {
        float inv = 1.f / (d_agg1[n * 16 + 15] + 1e-16f);
#pragma unroll
        for (int o = 0; o < 15; ++o) {
            h[o] = d_agg1[n * 16 + o] * inv + b1[o];
            d_h1[n * 16 + o] = h[o];
        }
    }
    __shared__ float ssum[15], ssq[15];
    if (threadIdx.x < 15) { ssum[threadIdx.x] = 0.f; ssq[threadIdx.x] = 0.f; }
    __syncthreads();
#pragma unroll
    for (int o = 0; o < 15; ++o) {
        float s = h[o], s2 = h[o] * h[o];
        for (int off = 16; off; off >>= 1) {
            s  += __shfl_down_sync(0xffffffffu, s, off);
            s2 += __shfl_down_sync(0xffffffffu, s2, off);
        }
        if ((threadIdx.x & 31) == 0) { atomicAdd(&ssum[o], s); atomicAdd(&ssq[o], s2); }
    }
    __syncthreads();
    if (threadIdx.x < 15)                               atomicAdd(&d_stats[threadIdx.x], ssum[threadIdx.x]);
    else if (threadIdx.x >= 16 && threadIdx.x < 31)     atomicAdd(&d_stats[threadIdx.x], ssq[threadIdx.x - 16]);
}

// ---------------- layer-2: inline BN-finalize, BN+ELU then [N,15] @ [15,48] ----------------
__global__ void __launch_bounds__(256) k_gemm2(const float* __restrict__ g1, const float* __restrict__ beta1,
                                               int n_nodes) {
    __shared__ float w2s[720];
    __shared__ float bns[15], bnb[15];
    if (threadIdx.x < 15) {
        int o = threadIdx.x;
        float invn = 1.f / (float)n_nodes;
        float mean = d_stats[o] * invn;
        float var  = d_stats[16 + o] * invn - mean * mean;
        float sc = g1[o] * rsqrtf(var + 1e-5f);
        bns[o] = sc;
        bnb[o] = beta1[o] - mean * sc;
    }
    for (int i = threadIdx.x; i < 720; i += 256) w2s[i] = d_CW2[i];
    __syncthreads();
    int n = blockIdx.x * 256 + threadIdx.x;
    if (n >= n_nodes) return;
    float x2[15];
#pragma unroll
    for (int o = 0; o < 15; ++o) {
        float v = d_h1[n * 16 + o] * bns[o] + bnb[o];
        x2[o] = (v > 0.f) ? v : expm1f(v);
    }
    float outv[48];
#pragma unroll
    for (int c = 0; c < 48; ++c) {
        float s = 0.f;
#pragma unroll
        for (int i = 0; i < 15; ++i) s += x2[i] * w2s[i * 48 + c];
        outv[c] = s;
    }
#pragma unroll
    for (int c = 0; c < 40; ++c) d_xt2[n * 64 + (c / 10) * 16 + (c % 10)] = outv[c];
#pragma unroll
    for (int r = 0; r < 4; ++r) {
        d_aq2[n * 4 + r] = outv[40 + r];
        d_xt2[n * 64 + r * 16 + 10] = outv[44 + r];   // ak2 packed
        d_xt2[n * 64 + r * 16 + 11] = 0.f;
    }
}

// ---------------- edge pass 2 ----------------
__global__ void __launch_bounds__(256) k_edge2(const int* __restrict__ ei, const int* __restrict__ et,
                                               const float* __restrict__ ea, int ne) {
    int e = blockIdx.x * 256 + threadIdx.x;
    if (e >= ne) return;
    int s = ei[e], d = ei[ne + e];
    int r = et[e];
    const float4* xp = reinterpret_cast<const float4*>(d_xt2 + ((size_t)s * 4 + r) * 16);
    float4 v0 = xp[0], v1 = xp[1], v2 = xp[2];   // v2.z = ak2[s,r]
    float a = d_aq2[d * 4 + r] + v2.z + ea[e] * d_c2;
    a = (a > 0.f) ? a : 0.2f * a;
    float ex = __expf(a);
    float* ag = d_agg2 + (size_t)d * 12;
    red4(ag + 0, ex * v0.x, ex * v0.y, ex * v0.z, ex * v0.w);
    red4(ag + 4, ex * v1.x, ex * v1.y, ex * v1.z, ex * v1.w);
    red4(ag + 8, ex * v2.x, ex * v2.y, ex, 0.f);             // slot10 = denom
}

// ---------------- post layer 2 ----------------
__global__ void __launch_bounds__(256) k_post2(const float* __restrict__ b2, int n_nodes) {
    int n = blockIdx.x * 256 + threadIdx.x;
    float h[10];
#pragma unroll
    for (int o = 0; o < 10; ++o) h[o] = 0.f;
    if (n < n_nodes) {
        float inv = 1.f / (d_agg2[n * 12 + 10] + 1e-16f);
#pragma unroll
        for (int o = 0; o < 10; ++o) {
            h[o] = d_agg2[n * 12 + o] * inv + b2[o];
            d_h2[n * 10 + o] = h[o];
        }
    }
    __shared__ float ssum[10], ssq[10];
    if (threadIdx.x < 10) { ssum[threadIdx.x] = 0.f; ssq[threadIdx.x] = 0.f; }
    __syncthreads();
#pragma unroll
    for (int o = 0; o < 10; ++o) {
        float s = h[o], s2 = h[o] * h[o];
        for (int off = 16; off; off >>= 1) {
            s  += __shfl_down_sync(0xffffffffu, s, off);
            s2 += __shfl_down_sync(0xffffffffu, s2, off);
        }
        if ((threadIdx.x & 31) == 0) { atomicAdd(&ssum[o], s); atomicAdd(&ssq[o], s2); }
    }
    __syncthreads();
    if (threadIdx.x < 10)                               atomicAdd(&d_stats[32 + threadIdx.x], ssum[threadIdx.x]);
    else if (threadIdx.x >= 16 && threadIdx.x < 26)     atomicAdd(&d_stats[48 + threadIdx.x - 16], ssq[threadIdx.x - 16]);
}

// ---------------- head (inline BN2 finalize) ----------------
__global__ void __launch_bounds__(256) k_head(const float* __restrict__ g2, const float* __restrict__ beta2,
                                              const float* __restrict__ wh, const float* __restrict__ bh,
                                              float* __restrict__ out, int n_nodes) {
    __shared__ float bns[10], bnb[10];
    if (threadIdx.x < 10) {
        int o = threadIdx.x;
        float invn = 1.f / (float)n_nodes;
        float mean = d_stats[32 + o] * invn;
        float var  = d_stats[48 + o] * invn - mean * mean;
        float sc = g2[o] * rsqrtf(var + 1e-5f);
        bns[o] = sc;
        bnb[o] = beta2[o] - mean * sc;
    }
    __syncthreads();
    int n = blockIdx.x * 256 + threadIdx.x;
    if (n >= n_nodes) return;
    float s = bh[0];
#pragma unroll
    for (int o = 0; o < 10; ++o) {
        float v = d_h2[n * 10 + o] * bns[o] + bnb[o];
        v = (v > 0.f) ? v : expm1f(v);
        s += v * wh[o];
    }
    out[n] = s;
}

// ---------------- launch ----------------
extern "C" void kernel_launch(void* const* d_in, const int* in_sizes, int n_in,
                              void* d_out, int out_size) {
    const float* x   = (const float*)d_in[0];
    const int*   ei  = (const int*)  d_in[1];
    const int*   et  = (const int*)  d_in[2];
    const float* ea  = (const float*)d_in[3];
    const float* W1  = (const float*)d_in[4];
    const float* q1  = (const float*)d_in[5];
    const float* k1  = (const float*)d_in[6];
    const float* e1  = (const float*)d_in[7];
    const float* We1 = (const float*)d_in[8];
    const float* b1  = (const float*)d_in[9];
    const float* W2  = (const float*)d_in[10];
    const float* q2  = (const float*)d_in[11];
    const float* k2  = (const float*)d_in[12];
    const float* e2  = (const float*)d_in[13];
    const float* We2 = (const float*)d_in[14];
    const float* b2  = (const float*)d_in[15];
    const float* g1  = (const float*)d_in[16];
    const float* bt1 = (const float*)d_in[17];
    const float* g2  = (const float*)d_in[18];
    const float* bt2 = (const float*)d_in[19];
    const float* wh  = (const float*)d_in[20];
    const float* bh  = (const float*)d_in[21];
    float* out = (float*)d_out;

    int n  = in_sizes[0] / FF;
    int ne = in_sizes[1] / 2;

    int init_tot = ZT + B1N + B2N;
    k_init<<<(init_tot + 255) / 256, 256>>>(W1, q1, k1, W2, q2, k2, We1, e1, We2, e2);
    k_gemm1<<<(n + 63) / 64, 256>>>(x, n);
    k_edge1<<<(ne + 255) / 256, 256>>>(ei, et, ea, ne);
    k_post1<<<(n + 255) / 256, 256>>>(b1, n);
    k_gemm2<<<(n + 255) / 256, 256>>>(g1, bt1, n);
    k_edge2<<<(ne + 255) / 256, 256>>>(ei, et, ea, ne);
    k_post2<<<(n + 255) / 256, 256>>>(b2, n);
    k_head<<<(n + 255) / 256, 256>>>(g2, bt2, wh, bh, out, n);
}